// round 1
// baseline (speedup 1.0000x reference)
#include <cuda_runtime.h>
#include <cstdint>

// SpikeFP32GELUExact: [B,S,D,32] float 0/1 pulses (MSB-first bits of fp32)
//  -> decode fp32 -> fp64 tanh-GELU (exact reference formula) -> fp32 RN
//  -> re-encode as 32 float 0/1 pulses.
//
// One thread per logical element: 128B contiguous load + 128B contiguous store.

__global__ void __launch_bounds__(256)
gelu_bits_kernel(const float4* __restrict__ in, float4* __restrict__ out, int n)
{
    int i = blockIdx.x * blockDim.x + threadIdx.x;
    if (i >= n) return;

    const float4* p = in + (size_t)i * 8;

    // Decode 32 MSB-first pulse floats -> uint32 bit pattern.
    unsigned u = 0;
#pragma unroll
    for (int j = 0; j < 8; j++) {
        float4 v = p[j];
        unsigned b0 = (v.x != 0.0f);
        unsigned b1 = (v.y != 0.0f);
        unsigned b2 = (v.z != 0.0f);
        unsigned b3 = (v.w != 0.0f);
        u = (u << 4) | (b0 << 3) | (b1 << 2) | (b2 << 1) | b3;
    }

    float xf = __uint_as_float(u);

    // Exact fp64 pipeline, same op order as the reference:
    // inner = x + 0.044715*x^3 ; z = c*inner ; e2z = exp(2z)
    // tanh = (e2z-1)/(e2z+1) ; res = 0.5*(x*(1+tanh))
    double x = (double)xf;
    double x_sq = x * x;
    double x_cubed = x_sq * x;
    double inner = x + 0.044715 * x_cubed;
    double z = 0.7978845608028654 * inner;
    double e2z = exp(2.0 * z);
    double tanh_z = (e2z - 1.0) / (e2z + 1.0);
    double res64 = 0.5 * (x * (1.0 + tanh_z));

    float rf = (float)res64;          // round-to-nearest downcast
    unsigned ur = __float_as_uint(rf);

    float4* q = out + (size_t)i * 8;
#pragma unroll
    for (int j = 0; j < 8; j++) {
        float4 o;
        o.x = ((ur >> (31 - (j * 4 + 0))) & 1u) ? 1.0f : 0.0f;
        o.y = ((ur >> (31 - (j * 4 + 1))) & 1u) ? 1.0f : 0.0f;
        o.z = ((ur >> (31 - (j * 4 + 2))) & 1u) ? 1.0f : 0.0f;
        o.w = ((ur >> (31 - (j * 4 + 3))) & 1u) ? 1.0f : 0.0f;
        q[j] = o;
    }
}

extern "C" void kernel_launch(void* const* d_in, const int* in_sizes, int n_in,
                              void* d_out, int out_size)
{
    (void)n_in;
    const float4* in = (const float4*)d_in[0];
    float4* out = (float4*)d_out;
    int n = in_sizes[0] / 32;          // logical elements (B*S*D = 4,194,304)
    (void)out_size;

    int threads = 256;
    int blocks = (n + threads - 1) / threads;
    gelu_bits_kernel<<<blocks, threads>>>(in, out, n);
}

// round 6
// speedup vs baseline: 1.0138x; 1.0138x over previous
#include <cuda_runtime.h>
#include <cstdint>

// SpikeFP32GELUExact: [B,S,D,32] float 0/1 pulses (MSB-first bits of fp32)
//  -> decode fp32 -> fp64 tanh-GELU (exact reference formula) -> fp32 RN
//  -> re-encode as 32 float 0/1 pulses.
//
// Warp-cooperative: one warp handles a tile of 32 elements (4KB in, 4KB out).
// Decode:  coalesced LDG.32 (one 128B line per instruction) + __ballot_sync.
// Encode:  coalesced STG.128 with __shfl_sync broadcast of result words.

__global__ void __launch_bounds__(256)
gelu_bits_kernel(const float* __restrict__ in, float4* __restrict__ out, int n_tiles)
{
    int gwarp = (blockIdx.x * blockDim.x + threadIdx.x) >> 5;
    int lane  = threadIdx.x & 31;
    if (gwarp >= n_tiles) return;

    const float* p = in + (size_t)gwarp * 1024;   // 32 elements * 32 floats

    // ---- decode: element e's 32-bit word via warp ballot ----
    // pulse float at idx l is bit (31-l) of the word; ballot bit l = lane l's
    // predicate, so word = __brev(ballot).
    unsigned u = 0;
#pragma unroll
    for (int e = 0; e < 32; e++) {
        float v = p[e * 32 + lane];                       // coalesced, 1 line
        unsigned b = __ballot_sync(0xffffffffu, v != 0.0f);
        if (lane == e) u = b;
    }
    u = __brev(u);

    // ---- compute: lane l owns element l; exact fp64 reference chain ----
    float xf = __uint_as_float(u);
    double x = (double)xf;
    double x_sq = x * x;
    double x_cubed = x_sq * x;
    double inner = x + 0.044715 * x_cubed;
    double z = 0.7978845608028654 * inner;
    double e2z = exp(2.0 * z);
    double tanh_z = (e2z - 1.0) / (e2z + 1.0);
    double res64 = 0.5 * (x * (1.0 + tanh_z));
    float rf = (float)res64;                              // RN downcast

    // rb bit idx == pulse float value at idx (MSB-first re-encode)
    unsigned rb = __brev(__float_as_uint(rf));

    // ---- encode: 8 coalesced STG.128 per warp-tile ----
    // float4 index f = j*32 + lane covers element e = f/8, quad q = f%8,
    // pulse idx = 4q + k  ->  bit (4q+k) of rb(e).
    float4* q = out + (size_t)gwarp * 256;                // 256 float4 per tile
#pragma unroll
    for (int j = 0; j < 8; j++) {
        int e = j * 4 + (lane >> 3);
        unsigned rr = __shfl_sync(0xffffffffu, rb, e);
        int qd = (lane & 7) * 4;
        float4 o;
        o.x = ((rr >> (qd + 0)) & 1u) ? 1.0f : 0.0f;
        o.y = ((rr >> (qd + 1)) & 1u) ? 1.0f : 0.0f;
        o.z = ((rr >> (qd + 2)) & 1u) ? 1.0f : 0.0f;
        o.w = ((rr >> (qd + 3)) & 1u) ? 1.0f : 0.0f;
        q[j * 32 + lane] = o;
    }
}

extern "C" void kernel_launch(void* const* d_in, const int* in_sizes, int n_in,
                              void* d_out, int out_size)
{
    (void)n_in; (void)out_size;
    const float* in = (const float*)d_in[0];
    float4* out = (float4*)d_out;
    int n_elem  = in_sizes[0] / 32;            // B*S*D = 4,194,304
    int n_tiles = (n_elem + 31) / 32;          // 32 elements per warp

    int threads = 256;                          // 8 warps -> 8 tiles per block
    int warps_per_block = threads / 32;
    int blocks = (n_tiles + warps_per_block - 1) / warps_per_block;
    gelu_bits_kernel<<<blocks, threads>>>(in, out, n_tiles);
}